// round 10
// baseline (speedup 1.0000x reference)
#include <cuda_runtime.h>
#include <cstdint>

// v: [8][1024][8][64] f32, w: [1][8][63] f32, out: [8][1024][8][64] f32
// out[n,j,h,d] = A[n,h,a,d] + B[n,h,b,d],  j = a*32+b,  l = c*32+e
//   A = bias @ R,  B = bias @ C
//   R[c,d] = sum_e v[n, c*32+e, h, d],  C[e,d] = sum_c v[n, c*32+e, h, d]
//   bias[h,j,k] = w[h, (32 - k + j) mod 63]
//
// 256 blocks = (n,h,q) x row-half G, G = %cluster_ctarank, 2-CTA clusters.
// Each CTA reads rows [G*512, G*512+512) x its 128B col slice once (contig).
// Partials exchanged by DSMEM *reads* after a cluster barrier. Each CTA
// stores j in [G*512, G*512+512). 2 blocks/SM -> read/store phase overlap.

#define THREADS 256

__device__ __forceinline__ uint32_t my_cluster_rank() {
    uint32_t r;
    asm("mov.u32 %0, %%cluster_ctarank;" : "=r"(r));
    return r;
}

__device__ __forceinline__ float4 dsmem_ld_f4(const void* local_smem, uint32_t peer_rank) {
    uint32_t la = (uint32_t)__cvta_generic_to_shared(local_smem);
    uint32_t ra;
    asm volatile("mapa.shared::cluster.u32 %0, %1, %2;"
                 : "=r"(ra) : "r"(la), "r"(peer_rank));
    float4 v;
    asm volatile("ld.shared::cluster.v4.f32 {%0, %1, %2, %3}, [%4];"
                 : "=f"(v.x), "=f"(v.y), "=f"(v.z), "=f"(v.w) : "r"(ra) : "memory");
    return v;
}

__global__ __launch_bounds__(THREADS, 2) __cluster_dims__(2, 1, 1)
void fused_kernel(const float4* __restrict__ v4,
                  const float*  __restrict__ w,
                  float4* __restrict__ out4) {
    int blk = blockIdx.x;              // 0..255; pair shares blk>>1
    int q = (blk >> 1) & 1;            // d-half: float4 cols [q*8, q*8+8)
    int h = (blk >> 2) & 7;
    int n = blk >> 5;                  // 0..7
    uint32_t G = my_cluster_rank();    // row-half AND j-half owner
    uint32_t peer = G ^ 1u;
    int tid = threadIdx.x;

    __shared__ float4 sRp[2][16][8];   // eh-split partials for own 16 c's
    __shared__ float4 sCh[32][8];      // own C partial (peer reads this)
    __shared__ float4 sRfull[32][8];   // own half written ph1-combine; peer half ph2
    __shared__ float4 sCfull[32][8];   // own + peer partials (ph2)
    __shared__ float4 sA[32][8], sB[32][8];
    __shared__ float  sb[32][33];

    const float4* base = v4 + ((size_t)n * 1024) * 128 + h * 16 + q * 8;

    int d4 = tid & 7;

    // ---- Pass A: R partials for own c-range. (rr, eh, d4), 16-deep chains ----
    {
        int rr = tid >> 4;             // 0..15
        int eh = (tid >> 3) & 1;       // 0..1
        int row0 = (int)G * 512 + rr * 32 + eh * 16;
        const float4* p = base + (size_t)row0 * 128 + d4;
        float4 acc = make_float4(0.f, 0.f, 0.f, 0.f);
        #pragma unroll
        for (int i = 0; i < 16; ++i) {
            float4 x = p[i * 128];
            acc.x += x.x; acc.y += x.y; acc.z += x.z; acc.w += x.w;
        }
        sRp[eh][rr][d4] = acc;
    }

    // ---- Pass B: C partial over own 16 c's. (e, d4), stride-32 rows (L1 hits) ----
    {
        int e = tid >> 3;              // 0..31
        const float4* p = base + (size_t)((int)G * 512 + e) * 128 + d4;
        float4 acc = make_float4(0.f, 0.f, 0.f, 0.f);
        #pragma unroll
        for (int cc = 0; cc < 16; ++cc) {
            float4 x = p[cc * 32 * 128];
            acc.x += x.x; acc.y += x.y; acc.z += x.z; acc.w += x.w;
        }
        sCh[e][d4] = acc;
    }

    // ---- bias tile (4/thread) ----
    #pragma unroll
    for (int idx = tid; idx < 1024; idx += THREADS) {
        int j = idx >> 5, k = idx & 31;
        sb[j][k] = w[h * 63 + ((32 - k + j) % 63)];
    }

    // ---- combine eh-partials into sRfull[own half] (128 threads) ----
    __syncthreads();
    if (tid < 128) {
        int rr = tid >> 3;
        float4 a = sRp[0][rr][d4], b = sRp[1][rr][d4];
        a.x += b.x; a.y += b.y; a.z += b.z; a.w += b.w;
        sRfull[(int)G * 16 + rr][d4] = a;
    }

    // ---- cluster barrier: publish sRfull[own], sCh to peer ----
    asm volatile("barrier.cluster.arrive.aligned;" ::: "memory");
    asm volatile("barrier.cluster.wait.aligned;"   ::: "memory");

    // ---- Phase 2: pull peer's partials (reads only; writes to fresh arrays) ----
    if (tid < 128) {
        int rr = tid >> 3;
        int pc = (int)peer * 16 + rr;                 // peer's c slots
        sRfull[pc][d4] = dsmem_ld_f4(&sRfull[pc][d4], peer);
    }
    {
        int e = tid >> 3;
        float4 mine = sCh[e][d4];
        float4 theirs = dsmem_ld_f4(&sCh[e][d4], peer);
        mine.x += theirs.x; mine.y += theirs.y;
        mine.z += theirs.z; mine.w += theirs.w;
        sCfull[e][d4] = mine;
    }
    __syncthreads();

    // ---- matvec: A = bias @ Rfull, B = bias @ Cfull. (r, d4) ----
    {
        int r = tid >> 3;
        float4 accA = make_float4(0.f, 0.f, 0.f, 0.f);
        float4 accB = make_float4(0.f, 0.f, 0.f, 0.f);
        #pragma unroll
        for (int k = 0; k < 32; ++k) {
            float f = sb[r][k];
            float4 x = sRfull[k][d4];
            float4 y = sCfull[k][d4];
            accA.x = fmaf(f, x.x, accA.x);
            accA.y = fmaf(f, x.y, accA.y);
            accA.z = fmaf(f, x.z, accA.z);
            accA.w = fmaf(f, x.w, accA.w);
            accB.x = fmaf(f, y.x, accB.x);
            accB.y = fmaf(f, y.y, accB.y);
            accB.z = fmaf(f, y.z, accB.z);
            accB.w = fmaf(f, y.w, accB.w);
        }
        sA[r][d4] = accA;
        sB[r][d4] = accB;
    }
    __syncthreads();

    // ---- store own j-half: j = G*512 + i*32 + r -> b = r (invariant), a = G*16+i ----
    {
        int r = tid >> 3;
        float4 y = sB[r][d4];          // loop-invariant
        float4* po = out4 + ((size_t)n * 1024 + (int)G * 512 + r) * 128 + h * 16 + q * 8 + d4;
        #pragma unroll
        for (int i = 0; i < 16; ++i) {
            float4 x = sA[(int)G * 16 + i][d4];
            x.x += y.x; x.y += y.y; x.z += y.z; x.w += y.w;
            __stcs(po + (size_t)i * 32 * 128, x);
        }
    }
}

extern "C" void kernel_launch(void* const* d_in, const int* in_sizes, int n_in,
                              void* d_out, int out_size) {
    const float* v = (const float*)d_in[0];
    const float* w = (const float*)d_in[1];
    if (n_in >= 2 && in_sizes[0] < in_sizes[1]) {
        const float* tmp = v; v = w; w = tmp;
    }

    fused_kernel<<<256, THREADS>>>((const float4*)v, w, (float4*)d_out);
}